// round 4
// baseline (speedup 1.0000x reference)
#include <cuda_runtime.h>
#include <cuda_bf16.h>
#include <cstdint>

#define NB 32768
#define NL 1024
#define NK 5
#define FEA 1028
#define MD 50
#define DD 32
#define SHRINKF 0.0025f
#define EPSF 1e-12f

// Extended contraction: K padded 50->64, tripled for bf16 split-precision.
// A segments [hi | hi | lo], B segments [hi | lo | hi]
#define KE   192
#define KE8  (KE / 8)      // 24 uint4 chunks per row
#define KP   200           // SMEM row pitch in bf16 (400B => conflict-free ldmatrix)

#define TM 128             // CTA rows
#define TN 128             // CTA cols

// Scratch (__device__ globals; allocation-free rule)
__device__ __align__(16) __nv_bfloat16 g_Ae[(size_t)NB * KE];   // 12.6 MB
__device__ __align__(16) __nv_bfloat16 g_Be[(size_t)NL * KE];   // 393 KB

__device__ __forceinline__ uint32_t smem_u32(const void* p) {
    uint32_t a;
    asm("{ .reg .u64 t; cvta.to.shared.u64 t, %1; cvt.u32.u64 %0, t; }"
        : "=r"(a) : "l"(p));
    return a;
}
__device__ __forceinline__ void ldmx4(uint32_t& r0, uint32_t& r1,
                                      uint32_t& r2, uint32_t& r3, uint32_t addr) {
    asm volatile("ldmatrix.sync.aligned.m8n8.x4.shared.b16 {%0,%1,%2,%3}, [%4];"
                 : "=r"(r0), "=r"(r1), "=r"(r2), "=r"(r3) : "r"(addr));
}
__device__ __forceinline__ void mma16816(float& c0, float& c1, float& c2, float& c3,
                                         uint32_t a0, uint32_t a1, uint32_t a2,
                                         uint32_t a3, uint32_t b0, uint32_t b1) {
    asm volatile(
        "mma.sync.aligned.m16n8k16.row.col.f32.bf16.bf16.f32 "
        "{%0,%1,%2,%3}, {%4,%5,%6,%7}, {%8,%9}, {%0,%1,%2,%3};"
        : "+f"(c0), "+f"(c1), "+f"(c2), "+f"(c3)
        : "r"(a0), "r"(a1), "r"(a2), "r"(a3), "r"(b0), "r"(b1));
}

// ---------------------------------------------------------------------------
// Kernel 1: fold transposed conv into mem_W, bf16-split, K-major [i][KE].
// ---------------------------------------------------------------------------
__global__ void k_prep(const float* __restrict__ mem_W,
                       const float* __restrict__ convt_w) {
    int i = blockIdx.x * blockDim.x + threadIdx.x;
    if (i >= NL) return;
    float c[NK];
#pragma unroll
    for (int t = 0; t < NK; t++) c[t] = convt_w[NK - 1 - t];
    for (int k = 0; k < 64; k++) {
        float v = 0.f;
        if (k < MD) {
#pragma unroll
            for (int t = 0; t < NK; t++) v += mem_W[k * FEA + i + t] * c[t];
        }
        __nv_bfloat16 hi = __float2bfloat16(v);
        __nv_bfloat16 lo = __float2bfloat16(v - __bfloat162float(hi));
        g_Be[(size_t)i * KE + k]       = hi;
        g_Be[(size_t)i * KE + 64 + k]  = lo;
        g_Be[(size_t)i * KE + 128 + k] = hi;
    }
}

// ---------------------------------------------------------------------------
// Kernel 2: att per row (one thread/row) -> bf16-split K-major [b][KE].
// ---------------------------------------------------------------------------
__global__ __launch_bounds__(128) void k_att(const float* __restrict__ date_vec,
                                             const float* __restrict__ date_W) {
    __shared__ float dW[MD * DD];
    int tid = threadIdx.x;
    for (int i = tid; i < MD * DD; i += 128) dW[i] = date_W[i];
    __syncthreads();

    int b = blockIdx.x * 128 + tid;
    float4 dv[8];
    const float4* dvp = (const float4*)(date_vec + (size_t)b * DD);
#pragma unroll
    for (int i = 0; i < 8; i++) dv[i] = dvp[i];

    float s[MD];
#pragma unroll
    for (int j = 0; j < MD; j++) {
        const float4* w4 = (const float4*)(dW + j * DD);
        float acc = 0.f;
#pragma unroll
        for (int i = 0; i < 8; i++) {
            float4 w = w4[i];
            acc += dv[i].x * w.x + dv[i].y * w.y + dv[i].z * w.z + dv[i].w * w.w;
        }
        s[j] = acc;
    }
    float m = -1e30f;
#pragma unroll
    for (int j = 0; j < MD; j++) m = fmaxf(m, s[j]);
    float sum = 0.f;
#pragma unroll
    for (int j = 0; j < MD; j++) { s[j] = expf(s[j] - m); sum += s[j]; }
    float inv = 1.f / sum;
    float sa = 0.f;
#pragma unroll
    for (int j = 0; j < MD; j++) {
        float a = s[j] * inv;
        float t = a - SHRINKF;
        float v = fmaxf(t, 0.f) * a / (fabsf(t) + EPSF);
        s[j] = v;
        sa += v;   // v >= 0
    }
    float inv2 = 1.f / (sa + EPSF);
    __nv_bfloat16* row = g_Ae + (size_t)b * KE;
#pragma unroll
    for (int j = 0; j < 64; j++) {
        float v = (j < MD) ? s[j] * inv2 : 0.f;
        __nv_bfloat16 hi = __float2bfloat16(v);
        __nv_bfloat16 lo = __float2bfloat16(v - __bfloat162float(hi));
        row[j]       = hi;
        row[64 + j]  = hi;
        row[128 + j] = lo;
    }
}

// ---------------------------------------------------------------------------
// Kernel 3: weight/bias per row (streams x). Writes into d_out tail.
// ---------------------------------------------------------------------------
__global__ __launch_bounds__(256) void k_wb(const float* __restrict__ x,
                                            const float* __restrict__ fcw_w,
                                            const float* __restrict__ fcw_b,
                                            const float* __restrict__ fcb_w,
                                            const float* __restrict__ fcb_b,
                                            float* __restrict__ out) {
    __shared__ float4 wS[256], bS[256];
    int tid = threadIdx.x;
    wS[tid] = ((const float4*)fcw_w)[tid];
    bS[tid] = ((const float4*)fcb_w)[tid];
    __syncthreads();

    int w = tid >> 5, l = tid & 31;
    int b = blockIdx.x * 8 + w;
    const float4* xr = (const float4*)(x + (size_t)b * NL);
    float wa = 0.f, ba = 0.f;
#pragma unroll
    for (int i = 0; i < 8; i++) {
        float4 xv = xr[i * 32 + l];
        float4 fw = wS[i * 32 + l];
        float4 fb = bS[i * 32 + l];
        wa += xv.x * fw.x + xv.y * fw.y + xv.z * fw.z + xv.w * fw.w;
        ba += xv.x * fb.x + xv.y * fb.y + xv.z * fb.z + xv.w * fb.w;
    }
#pragma unroll
    for (int o = 16; o; o >>= 1) {
        wa += __shfl_xor_sync(~0u, wa, o);
        ba += __shfl_xor_sync(~0u, ba, o);
    }
    if (l == 0) {
        out[(size_t)NB * NL + b]      = tanhf(wa + fcw_b[0]) * 0.5f + 1.0f;
        out[(size_t)NB * NL + NB + b] = tanhf(ba + fcb_b[0]) * 0.5f;
    }
}

// ---------------------------------------------------------------------------
// Kernel 4: warp-MMA bf16-split GEMM + fused affine epilogue.
// CTA 128x128, 8 warps (2 M x 4 N), warp tile 64x32, k-steps of 16 (12 total).
// ---------------------------------------------------------------------------
#define SM_A_B   (TM * KP * 2)                   // 51200
#define SM_B_B   (TN * KP * 2)                   // 51200
#define OFF_W    (SM_A_B + SM_B_B)               // 102400
#define OFF_BI   (OFF_W + TM * 4)
#define SMEM_REQ (OFF_BI + TM * 4)               // 103424

__global__ __launch_bounds__(256, 2) void k_gemm(float* __restrict__ out) {
    extern __shared__ char smc[];
    __nv_bfloat16* As = (__nv_bfloat16*)smc;
    __nv_bfloat16* Bs = (__nv_bfloat16*)(smc + SM_A_B);
    float* wS  = (float*)(smc + OFF_W);
    float* biS = (float*)(smc + OFF_BI);

    int tid = threadIdx.x;
    int wid = tid >> 5, lane = tid & 31;
    int brow = blockIdx.y * TM;
    int bcol = blockIdx.x * TN;

    // Fill A tile (coalesced uint4, padded pitch KP)
    for (int i = tid; i < TM * KE8; i += 256) {
        int r = i / KE8, c8 = i - r * KE8;
        uint4 v = *(const uint4*)&g_Ae[(size_t)(brow + r) * KE + c8 * 8];
        *(uint4*)&As[r * KP + c8 * 8] = v;
    }
    // Fill B tile
    for (int i = tid; i < TN * KE8; i += 256) {
        int r = i / KE8, c8 = i - r * KE8;
        uint4 v = *(const uint4*)&g_Be[(size_t)(bcol + r) * KE + c8 * 8];
        *(uint4*)&Bs[r * KP + c8 * 8] = v;
    }
    if (tid < TM) {
        wS[tid]  = out[(size_t)NB * NL + brow + tid];
        biS[tid] = out[(size_t)NB * NL + NB + brow + tid];
    }
    __syncthreads();

    int warp_m = wid >> 2;          // 0..1
    int warp_n = wid & 3;           // 0..3
    int m0 = warp_m * 64;
    int n0 = warp_n * 32;

    uint32_t aBase = smem_u32(As);
    uint32_t bBase = smem_u32(Bs);

    // ldmatrix lane addressing (constant per thread)
    int a_row = lane & 15;
    int a_col8 = (lane >> 4) * 8;
    int b_row = (lane & 7) + ((lane >> 4) << 3);
    int b_col8 = ((lane >> 3) & 1) * 8;

    float acc[4][4][4];
#pragma unroll
    for (int mf = 0; mf < 4; mf++)
#pragma unroll
        for (int nf = 0; nf < 4; nf++)
#pragma unroll
            for (int q = 0; q < 4; q++) acc[mf][nf][q] = 0.f;

#pragma unroll
    for (int ks = 0; ks < KE / 16; ks++) {
        int k0 = ks * 16;
        uint32_t a[4][4];
#pragma unroll
        for (int mf = 0; mf < 4; mf++) {
            uint32_t addr = aBase +
                ((m0 + mf * 16 + a_row) * KP + k0 + a_col8) * 2;
            ldmx4(a[mf][0], a[mf][1], a[mf][2], a[mf][3], addr);
        }
        uint32_t bfr[4][2];   // 4 n8 fragments, 2 regs each
#pragma unroll
        for (int h = 0; h < 2; h++) {
            uint32_t addr = bBase +
                ((n0 + h * 16 + b_row) * KP + k0 + b_col8) * 2;
            ldmx4(bfr[h * 2][0], bfr[h * 2][1], bfr[h * 2 + 1][0], bfr[h * 2 + 1][1],
                  addr);
        }
#pragma unroll
        for (int mf = 0; mf < 4; mf++)
#pragma unroll
            for (int nf = 0; nf < 4; nf++)
                mma16816(acc[mf][nf][0], acc[mf][nf][1], acc[mf][nf][2],
                         acc[mf][nf][3], a[mf][0], a[mf][1], a[mf][2], a[mf][3],
                         bfr[nf][0], bfr[nf][1]);
    }

    // Epilogue: *weight + bias, float2 stores
    int g = lane >> 2, tg = lane & 3;
#pragma unroll
    for (int mf = 0; mf < 4; mf++) {
        int r0i = m0 + mf * 16 + g;
        int r1i = r0i + 8;
        float w0 = wS[r0i], b0 = biS[r0i];
        float w1 = wS[r1i], b1 = biS[r1i];
        float* o0 = out + (size_t)(brow + r0i) * NL + bcol + n0 + tg * 2;
        float* o1 = out + (size_t)(brow + r1i) * NL + bcol + n0 + tg * 2;
#pragma unroll
        for (int nf = 0; nf < 4; nf++) {
            float2 v0, v1;
            v0.x = acc[mf][nf][0] * w0 + b0;
            v0.y = acc[mf][nf][1] * w0 + b0;
            v1.x = acc[mf][nf][2] * w1 + b1;
            v1.y = acc[mf][nf][3] * w1 + b1;
            *(float2*)(o0 + nf * 8) = v0;
            *(float2*)(o1 + nf * 8) = v1;
        }
    }
}

// ---------------------------------------------------------------------------
extern "C" void kernel_launch(void* const* d_in, const int* in_sizes, int n_in,
                              void* d_out, int out_size) {
    const float* x        = (const float*)d_in[0];
    const float* date_vec = (const float*)d_in[1];
    // d_in[2] (conv_w) is dead code in the reference
    const float* convt_w  = (const float*)d_in[3];
    const float* mem_W    = (const float*)d_in[4];
    const float* date_W   = (const float*)d_in[5];
    const float* fcw_w    = (const float*)d_in[6];
    const float* fcw_b    = (const float*)d_in[7];
    const float* fcb_w    = (const float*)d_in[8];
    const float* fcb_b    = (const float*)d_in[9];
    float* out = (float*)d_out;

    cudaFuncSetAttribute(k_gemm, cudaFuncAttributeMaxDynamicSharedMemorySize,
                         SMEM_REQ);

    k_prep<<<(NL + 255) / 256, 256>>>(mem_W, convt_w);
    k_att<<<NB / 128, 128>>>(date_vec, date_W);
    k_wb<<<NB / 8, 256>>>(x, fcw_w, fcw_b, fcb_w, fcb_b, out);
    dim3 g(NL / TN, NB / TM);
    k_gemm<<<g, 256, SMEM_REQ>>>(out);
}

// round 5
// speedup vs baseline: 2.9195x; 2.9195x over previous
#include <cuda_runtime.h>
#include <cuda_bf16.h>
#include <cstdint>

#define NB 32768
#define NL 1024
#define NK 5
#define FEA 1028
#define MD 50
#define DD 32
#define SHRINKF 0.0025f
#define EPSF 1e-12f

// Plain bf16 contraction: K padded 50->64. (Split-precision unnecessary: the
// GEMM term is ~1% of output magnitude; bf16 error dilutes to ~1e-5 global.)
#define KE   64
#define KE8  (KE / 8)      // 8 uint4 chunks per row
#define KP   72            // SMEM pitch in bf16 (144B -> conflict-free ldmatrix)

#define TM 128             // CTA rows
#define TN 128             // CTA cols

// Scratch (__device__ globals; allocation-free rule)
__device__ __align__(16) __nv_bfloat16 g_Ae[(size_t)NB * KE];   // 4.2 MB
__device__ __align__(16) __nv_bfloat16 g_Be[(size_t)NL * KE];   // 131 KB

__device__ __forceinline__ uint32_t smem_u32(const void* p) {
    uint32_t a;
    asm("{ .reg .u64 t; cvta.to.shared.u64 t, %1; cvt.u32.u64 %0, t; }"
        : "=r"(a) : "l"(p));
    return a;
}
__device__ __forceinline__ void ldmx4(uint32_t& r0, uint32_t& r1,
                                      uint32_t& r2, uint32_t& r3, uint32_t addr) {
    asm volatile("ldmatrix.sync.aligned.m8n8.x4.shared.b16 {%0,%1,%2,%3}, [%4];"
                 : "=r"(r0), "=r"(r1), "=r"(r2), "=r"(r3) : "r"(addr));
}
__device__ __forceinline__ void mma16816(float& c0, float& c1, float& c2, float& c3,
                                         uint32_t a0, uint32_t a1, uint32_t a2,
                                         uint32_t a3, uint32_t b0, uint32_t b1) {
    asm volatile(
        "mma.sync.aligned.m16n8k16.row.col.f32.bf16.bf16.f32 "
        "{%0,%1,%2,%3}, {%4,%5,%6,%7}, {%8,%9}, {%0,%1,%2,%3};"
        : "+f"(c0), "+f"(c1), "+f"(c2), "+f"(c3)
        : "r"(a0), "r"(a1), "r"(a2), "r"(a3), "r"(b0), "r"(b1));
}

// ---------------------------------------------------------------------------
// Kernel 1: fold transposed conv into mem_W -> bf16, K-major [i][KE].
// ---------------------------------------------------------------------------
__global__ void k_prep(const float* __restrict__ mem_W,
                       const float* __restrict__ convt_w) {
    int i = blockIdx.x * blockDim.x + threadIdx.x;
    if (i >= NL) return;
    float c[NK];
#pragma unroll
    for (int t = 0; t < NK; t++) c[t] = convt_w[NK - 1 - t];
#pragma unroll
    for (int k = 0; k < KE; k++) {
        float v = 0.f;
        if (k < MD) {
#pragma unroll
            for (int t = 0; t < NK; t++) v += mem_W[k * FEA + i + t] * c[t];
        }
        g_Be[(size_t)i * KE + k] = __float2bfloat16(v);
    }
}

// ---------------------------------------------------------------------------
// Kernel 2: att per row (one thread/row) -> bf16 K-major, SMEM-staged.
// ---------------------------------------------------------------------------
__global__ __launch_bounds__(128) void k_att(const float* __restrict__ date_vec,
                                             const float* __restrict__ date_W) {
    __shared__ float dW[MD * DD];
    __shared__ __align__(16) __nv_bfloat16 stage[128 * KE];  // 16 KB
    int tid = threadIdx.x;
    for (int i = tid; i < MD * DD; i += 128) dW[i] = date_W[i];
    __syncthreads();

    int b = blockIdx.x * 128 + tid;
    float4 dv[8];
    const float4* dvp = (const float4*)(date_vec + (size_t)b * DD);
#pragma unroll
    for (int i = 0; i < 8; i++) dv[i] = dvp[i];

    float s[MD];
#pragma unroll
    for (int j = 0; j < MD; j++) {
        const float4* w4 = (const float4*)(dW + j * DD);
        float acc = 0.f;
#pragma unroll
        for (int i = 0; i < 8; i++) {
            float4 w = w4[i];
            acc += dv[i].x * w.x + dv[i].y * w.y + dv[i].z * w.z + dv[i].w * w.w;
        }
        s[j] = acc;
    }
    float m = -1e30f;
#pragma unroll
    for (int j = 0; j < MD; j++) m = fmaxf(m, s[j]);
    float sum = 0.f;
#pragma unroll
    for (int j = 0; j < MD; j++) { s[j] = expf(s[j] - m); sum += s[j]; }
    float inv = 1.f / sum;
    float sa = 0.f;
#pragma unroll
    for (int j = 0; j < MD; j++) {
        float a = s[j] * inv;
        float t = a - SHRINKF;
        float v = fmaxf(t, 0.f) * a / (fabsf(t) + EPSF);
        s[j] = v;
        sa += v;   // v >= 0
    }
    float inv2 = 1.f / (sa + EPSF);
#pragma unroll
    for (int j = 0; j < KE; j++) {
        float v = (j < MD) ? s[j] * inv2 : 0.f;
        stage[tid * KE + j] = __float2bfloat16(v);
    }
    __syncthreads();
    // Coalesced bulk copy to global (block covers 128 consecutive rows)
    const uint4* st4 = (const uint4*)stage;
    uint4* gA4 = (uint4*)g_Ae;
    size_t base = (size_t)blockIdx.x * 128 * KE8;
    for (int i = tid; i < 128 * KE8; i += 128) gA4[base + i] = st4[i];
}

// ---------------------------------------------------------------------------
// Kernel 3: weight/bias per row (streams x). Writes into d_out tail.
// ---------------------------------------------------------------------------
__global__ __launch_bounds__(256) void k_wb(const float* __restrict__ x,
                                            const float* __restrict__ fcw_w,
                                            const float* __restrict__ fcw_b,
                                            const float* __restrict__ fcb_w,
                                            const float* __restrict__ fcb_b,
                                            float* __restrict__ out) {
    __shared__ float4 wS[256], bS[256];
    int tid = threadIdx.x;
    wS[tid] = ((const float4*)fcw_w)[tid];
    bS[tid] = ((const float4*)fcb_w)[tid];
    __syncthreads();

    int w = tid >> 5, l = tid & 31;
    int b = blockIdx.x * 8 + w;
    const float4* xr = (const float4*)(x + (size_t)b * NL);
    float wa = 0.f, ba = 0.f;
#pragma unroll
    for (int i = 0; i < 8; i++) {
        float4 xv = xr[i * 32 + l];
        float4 fw = wS[i * 32 + l];
        float4 fb = bS[i * 32 + l];
        wa += xv.x * fw.x + xv.y * fw.y + xv.z * fw.z + xv.w * fw.w;
        ba += xv.x * fb.x + xv.y * fb.y + xv.z * fb.z + xv.w * fb.w;
    }
#pragma unroll
    for (int o = 16; o; o >>= 1) {
        wa += __shfl_xor_sync(~0u, wa, o);
        ba += __shfl_xor_sync(~0u, ba, o);
    }
    if (l == 0) {
        out[(size_t)NB * NL + b]      = tanhf(wa + fcw_b[0]) * 0.5f + 1.0f;
        out[(size_t)NB * NL + NB + b] = tanhf(ba + fcb_b[0]) * 0.5f;
    }
}

// ---------------------------------------------------------------------------
// Kernel 4: warp-MMA bf16 GEMM + fused affine epilogue.
// CTA 128x128, 8 warps (2 M x 4 N), warp tile 64x32, 4 k-steps of 16.
// ---------------------------------------------------------------------------
#define SM_A_B   (TM * KP * 2)                   // 18432
#define SM_B_B   (TN * KP * 2)                   // 18432
#define OFF_W    (SM_A_B + SM_B_B)               // 36864
#define OFF_BI   (OFF_W + TM * 4)
#define SMEM_REQ (OFF_BI + TM * 4)               // 37888

__global__ __launch_bounds__(256, 2) void k_gemm(float* __restrict__ out) {
    extern __shared__ char smc[];
    __nv_bfloat16* As = (__nv_bfloat16*)smc;
    __nv_bfloat16* Bs = (__nv_bfloat16*)(smc + SM_A_B);
    float* wS  = (float*)(smc + OFF_W);
    float* biS = (float*)(smc + OFF_BI);

    int tid = threadIdx.x;
    int wid = tid >> 5, lane = tid & 31;
    int brow = blockIdx.y * TM;
    int bcol = blockIdx.x * TN;

    // Fill A tile (coalesced uint4, padded pitch KP)
    for (int i = tid; i < TM * KE8; i += 256) {
        int r = i >> 3, c8 = i & 7;
        uint4 v = *(const uint4*)&g_Ae[(size_t)(brow + r) * KE + c8 * 8];
        *(uint4*)&As[r * KP + c8 * 8] = v;
    }
    // Fill B tile
    for (int i = tid; i < TN * KE8; i += 256) {
        int r = i >> 3, c8 = i & 7;
        uint4 v = *(const uint4*)&g_Be[(size_t)(bcol + r) * KE + c8 * 8];
        *(uint4*)&Bs[r * KP + c8 * 8] = v;
    }
    if (tid < TM) {
        wS[tid]  = out[(size_t)NB * NL + brow + tid];
        biS[tid] = out[(size_t)NB * NL + NB + brow + tid];
    }
    __syncthreads();

    int warp_m = wid >> 2;          // 0..1
    int warp_n = wid & 3;           // 0..3
    int m0 = warp_m * 64;
    int n0 = warp_n * 32;

    uint32_t aBase = smem_u32(As);
    uint32_t bBase = smem_u32(Bs);

    // ldmatrix lane addressing (constant per thread)
    int a_row = lane & 15;
    int a_col8 = (lane >> 4) * 8;
    int b_row = (lane & 7) + ((lane >> 4) << 3);
    int b_col8 = ((lane >> 3) & 1) * 8;

    float acc[4][4][4];
#pragma unroll
    for (int mf = 0; mf < 4; mf++)
#pragma unroll
        for (int nf = 0; nf < 4; nf++)
#pragma unroll
            for (int q = 0; q < 4; q++) acc[mf][nf][q] = 0.f;

#pragma unroll
    for (int ks = 0; ks < KE / 16; ks++) {
        int k0 = ks * 16;
        uint32_t a[4][4];
#pragma unroll
        for (int mf = 0; mf < 4; mf++) {
            uint32_t addr = aBase +
                ((m0 + mf * 16 + a_row) * KP + k0 + a_col8) * 2;
            ldmx4(a[mf][0], a[mf][1], a[mf][2], a[mf][3], addr);
        }
        uint32_t bfr[4][2];   // 4 n8 fragments, 2 regs each
#pragma unroll
        for (int h = 0; h < 2; h++) {
            uint32_t addr = bBase +
                ((n0 + h * 16 + b_row) * KP + k0 + b_col8) * 2;
            ldmx4(bfr[h * 2][0], bfr[h * 2][1], bfr[h * 2 + 1][0], bfr[h * 2 + 1][1],
                  addr);
        }
#pragma unroll
        for (int mf = 0; mf < 4; mf++)
#pragma unroll
            for (int nf = 0; nf < 4; nf++)
                mma16816(acc[mf][nf][0], acc[mf][nf][1], acc[mf][nf][2],
                         acc[mf][nf][3], a[mf][0], a[mf][1], a[mf][2], a[mf][3],
                         bfr[nf][0], bfr[nf][1]);
    }

    // Epilogue: *weight + bias, float2 stores
    int g = lane >> 2, tg = lane & 3;
#pragma unroll
    for (int mf = 0; mf < 4; mf++) {
        int r0i = m0 + mf * 16 + g;
        int r1i = r0i + 8;
        float w0 = wS[r0i], b0 = biS[r0i];
        float w1 = wS[r1i], b1 = biS[r1i];
        float* o0 = out + (size_t)(brow + r0i) * NL + bcol + n0 + tg * 2;
        float* o1 = out + (size_t)(brow + r1i) * NL + bcol + n0 + tg * 2;
#pragma unroll
        for (int nf = 0; nf < 4; nf++) {
            float2 v0, v1;
            v0.x = acc[mf][nf][0] * w0 + b0;
            v0.y = acc[mf][nf][1] * w0 + b0;
            v1.x = acc[mf][nf][2] * w1 + b1;
            v1.y = acc[mf][nf][3] * w1 + b1;
            *(float2*)(o0 + nf * 8) = v0;
            *(float2*)(o1 + nf * 8) = v1;
        }
    }
}

// ---------------------------------------------------------------------------
extern "C" void kernel_launch(void* const* d_in, const int* in_sizes, int n_in,
                              void* d_out, int out_size) {
    const float* x        = (const float*)d_in[0];
    const float* date_vec = (const float*)d_in[1];
    // d_in[2] (conv_w) is dead code in the reference
    const float* convt_w  = (const float*)d_in[3];
    const float* mem_W    = (const float*)d_in[4];
    const float* date_W   = (const float*)d_in[5];
    const float* fcw_w    = (const float*)d_in[6];
    const float* fcw_b    = (const float*)d_in[7];
    const float* fcb_w    = (const float*)d_in[8];
    const float* fcb_b    = (const float*)d_in[9];
    float* out = (float*)d_out;

    cudaFuncSetAttribute(k_gemm, cudaFuncAttributeMaxDynamicSharedMemorySize,
                         SMEM_REQ);

    k_prep<<<(NL + 255) / 256, 256>>>(mem_W, convt_w);
    k_att<<<NB / 128, 128>>>(date_vec, date_W);
    k_wb<<<NB / 8, 256>>>(x, fcw_w, fcw_b, fcb_w, fcb_b, out);
    dim3 g(NL / TN, NB / TM);
    k_gemm<<<g, 256, SMEM_REQ>>>(out);
}

// round 6
// speedup vs baseline: 3.6335x; 1.2446x over previous
#include <cuda_runtime.h>
#include <cuda_bf16.h>
#include <cstdint>

#define NB 32768
#define NL 1024
#define NK 5
#define FEA 1028
#define MD 50
#define DD 32
#define SHRINKF 0.0025f
#define EPSF 1e-12f

#define KE   64            // K padded 50->64, plain bf16
#define KE8  (KE / 8)
#define KP   72            // SMEM pitch in bf16 (144B -> conflict-free ldmatrix)

#define TM 128             // rows per CTA
#define TN 128             // cols per chunk
#define NCHUNK (NL / TN)   // 8

// Scratch (__device__ global; allocation-free rule)
__device__ __align__(16) __nv_bfloat16 g_Be[(size_t)NL * KE];   // 131 KB

__device__ __forceinline__ uint32_t smem_u32(const void* p) {
    uint32_t a;
    asm("{ .reg .u64 t; cvta.to.shared.u64 t, %1; cvt.u32.u64 %0, t; }"
        : "=r"(a) : "l"(p));
    return a;
}
__device__ __forceinline__ void ldmx4(uint32_t& r0, uint32_t& r1,
                                      uint32_t& r2, uint32_t& r3, uint32_t addr) {
    asm volatile("ldmatrix.sync.aligned.m8n8.x4.shared.b16 {%0,%1,%2,%3}, [%4];"
                 : "=r"(r0), "=r"(r1), "=r"(r2), "=r"(r3) : "r"(addr));
}
__device__ __forceinline__ void mma16816(float& c0, float& c1, float& c2, float& c3,
                                         uint32_t a0, uint32_t a1, uint32_t a2,
                                         uint32_t a3, uint32_t b0, uint32_t b1) {
    asm volatile(
        "mma.sync.aligned.m16n8k16.row.col.f32.bf16.bf16.f32 "
        "{%0,%1,%2,%3}, {%4,%5,%6,%7}, {%8,%9}, {%0,%1,%2,%3};"
        : "+f"(c0), "+f"(c1), "+f"(c2), "+f"(c3)
        : "r"(a0), "r"(a1), "r"(a2), "r"(a3), "r"(b0), "r"(b1));
}
__device__ __forceinline__ void cpa16(uint32_t dst, const void* src) {
    asm volatile("cp.async.cg.shared.global [%0], [%1], 16;" :: "r"(dst), "l"(src));
}
__device__ __forceinline__ void cpa_commit() {
    asm volatile("cp.async.commit_group;" ::: "memory");
}
template <int N>
__device__ __forceinline__ void cpa_wait() {
    asm volatile("cp.async.wait_group %0;" :: "n"(N) : "memory");
}

// ---------------------------------------------------------------------------
// Kernel 1: fold transposed conv into mem_W -> bf16, K-major [i][KE].
// ---------------------------------------------------------------------------
__global__ void k_prep(const float* __restrict__ mem_W,
                       const float* __restrict__ convt_w) {
    int i = blockIdx.x * blockDim.x + threadIdx.x;
    if (i >= NL) return;
    float c[NK];
#pragma unroll
    for (int t = 0; t < NK; t++) c[t] = convt_w[NK - 1 - t];
#pragma unroll
    for (int k = 0; k < KE; k++) {
        float v = 0.f;
        if (k < MD) {
#pragma unroll
            for (int t = 0; t < NK; t++) v += mem_W[k * FEA + i + t] * c[t];
        }
        g_Be[(size_t)i * KE + k] = __float2bfloat16(v);
    }
}

// ---------------------------------------------------------------------------
// Fused kernel: per CTA of 128 rows —
//   (a) att -> A tile in SMEM (bf16, KP pitch)
//   (b) weight/bias from x (warp-per-row), into SMEM + out tail
//   (c) 8 column chunks: cp.async B tile (double buffered), warp-MMA,
//       fused affine epilogue store.
// ---------------------------------------------------------------------------
#define SM_A_B   (TM * KP * 2)                        // 18432
#define SM_B_B   (TM * KP * 2)                        // per buffer, 18432
#define OFF_B0   SM_A_B
#define OFF_B1   (SM_A_B + SM_B_B)
#define OFF_FCW  (OFF_B1 + SM_B_B)                    // 55296
#define OFF_FCB  (OFF_FCW + NL * 4)
#define OFF_W    (OFF_FCB + NL * 4)
#define OFF_BI   (OFF_W + TM * 4)
#define SMEM_REQ (OFF_BI + TM * 4)                    // 64512

__global__ __launch_bounds__(256, 2) void k_fused(
    const float* __restrict__ x,
    const float* __restrict__ date_vec,
    const float* __restrict__ date_W,
    const float* __restrict__ fcw_w,
    const float* __restrict__ fcw_b,
    const float* __restrict__ fcb_w,
    const float* __restrict__ fcb_b,
    float* __restrict__ out) {
    extern __shared__ char smc[];
    __nv_bfloat16* As = (__nv_bfloat16*)smc;
    float* fcwS = (float*)(smc + OFF_FCW);
    float* fcbS = (float*)(smc + OFF_FCB);
    float* wS   = (float*)(smc + OFF_W);
    float* biS  = (float*)(smc + OFF_BI);
    float* dW   = (float*)(smc + OFF_B1);   // temp: date_W in B buffer 1

    int tid = threadIdx.x;
    int wid = tid >> 5, lane = tid & 31;
    int brow = blockIdx.x * TM;
    uint32_t smBase = smem_u32(smc);

    // --- Prefetch B chunk 0 into buffer 0 (async, not needed until loop) ---
    for (int i = tid; i < TM * KE8; i += 256) {
        int r = i >> 3, j = i & 7;
        cpa16(smBase + OFF_B0 + (r * KP + j * 8) * 2,
              &g_Be[(size_t)r * KE + j * 8]);
    }
    cpa_commit();

    // --- Load small weights into SMEM ---
    {
        float4* f4 = (float4*)fcwS;
        float4* g4 = (float4*)fcbS;
        f4[tid] = ((const float4*)fcw_w)[tid];
        g4[tid] = ((const float4*)fcb_w)[tid];
        for (int i = tid; i < MD * DD; i += 256) dW[i] = date_W[i];
    }
    __syncthreads();

    // --- Phase A: attention -> A tile (one thread per row, threads 0..127) ---
    if (tid < TM) {
        int b = brow + tid;
        float4 dv[8];
        const float4* dvp = (const float4*)(date_vec + (size_t)b * DD);
#pragma unroll
        for (int i = 0; i < 8; i++) dv[i] = dvp[i];
        float s[MD];
#pragma unroll
        for (int j = 0; j < MD; j++) {
            const float4* w4 = (const float4*)(dW + j * DD);
            float acc = 0.f;
#pragma unroll
            for (int i = 0; i < 8; i++) {
                float4 w = w4[i];
                acc += dv[i].x * w.x + dv[i].y * w.y + dv[i].z * w.z + dv[i].w * w.w;
            }
            s[j] = acc;
        }
        float m = -1e30f;
#pragma unroll
        for (int j = 0; j < MD; j++) m = fmaxf(m, s[j]);
        float sum = 0.f;
#pragma unroll
        for (int j = 0; j < MD; j++) { s[j] = expf(s[j] - m); sum += s[j]; }
        float inv = 1.f / sum;
        float sa = 0.f;
#pragma unroll
        for (int j = 0; j < MD; j++) {
            float a = s[j] * inv;
            float t = a - SHRINKF;
            float v = fmaxf(t, 0.f) * a / (fabsf(t) + EPSF);
            s[j] = v;
            sa += v;   // v >= 0
        }
        float inv2 = 1.f / (sa + EPSF);
        __nv_bfloat16* row = As + tid * KP;
#pragma unroll
        for (int j = 0; j < KE; j++)
            row[j] = __float2bfloat16(j < MD ? s[j] * inv2 : 0.f);
    }

    // --- Phase W: weight/bias (warp per row, 16 rows per warp) ---
    {
        const float4* fw4 = (const float4*)fcwS;
        const float4* fb4 = (const float4*)fcbS;
        float w0c = fcw_b[0], b0c = fcb_b[0];
#pragma unroll 1
        for (int r = 0; r < 16; r++) {
            int row = wid * 16 + r;
            const float4* xr = (const float4*)(x + (size_t)(brow + row) * NL);
            float wa = 0.f, ba = 0.f;
#pragma unroll
            for (int i = 0; i < 8; i++) {
                float4 xv = xr[i * 32 + lane];
                float4 fw = fw4[i * 32 + lane];
                float4 fb = fb4[i * 32 + lane];
                wa += xv.x * fw.x + xv.y * fw.y + xv.z * fw.z + xv.w * fw.w;
                ba += xv.x * fb.x + xv.y * fb.y + xv.z * fb.z + xv.w * fb.w;
            }
#pragma unroll
            for (int o = 16; o; o >>= 1) {
                wa += __shfl_xor_sync(~0u, wa, o);
                ba += __shfl_xor_sync(~0u, ba, o);
            }
            if (lane == 0) {
                float wv = tanhf(wa + w0c) * 0.5f + 1.0f;
                float bv = tanhf(ba + b0c) * 0.5f;
                wS[row] = wv;
                biS[row] = bv;
                out[(size_t)NB * NL + brow + row] = wv;
                out[(size_t)NB * NL + NB + brow + row] = bv;
            }
        }
    }
    __syncthreads();   // A tile, wS/biS ready; dW dead (buf1 reusable)

    // --- Phase G: chunk loop with double-buffered B ---
    int warp_m = wid >> 2, warp_n = wid & 3;
    int m0 = warp_m * 64, n0 = warp_n * 32;
    uint32_t aBase = smBase;

    int a_row = lane & 15;
    int a_col8 = (lane >> 4) * 8;
    int b_row = (lane & 7) + ((lane >> 4) << 3);
    int b_col8 = ((lane >> 3) & 1) * 8;

#pragma unroll 1
    for (int c = 0; c < NCHUNK; c++) {
        // Prefetch next chunk into the other buffer
        if (c + 1 < NCHUNK) {
            uint32_t dstb = smBase + ((c + 1) & 1 ? OFF_B1 : OFF_B0);
            for (int i = tid; i < TM * KE8; i += 256) {
                int r = i >> 3, j = i & 7;
                cpa16(dstb + (r * KP + j * 8) * 2,
                      &g_Be[(size_t)((c + 1) * TN + r) * KE + j * 8]);
            }
            cpa_commit();
            cpa_wait<1>();
        } else {
            cpa_wait<0>();
        }
        __syncthreads();   // current buffer ready for all warps

        uint32_t bBase = smBase + (c & 1 ? OFF_B1 : OFF_B0);

        float acc[4][4][4];
#pragma unroll
        for (int mf = 0; mf < 4; mf++)
#pragma unroll
            for (int nf = 0; nf < 4; nf++)
#pragma unroll
                for (int q = 0; q < 4; q++) acc[mf][nf][q] = 0.f;

#pragma unroll
        for (int ks = 0; ks < KE / 16; ks++) {
            int k0 = ks * 16;
            uint32_t a[4][4];
#pragma unroll
            for (int mf = 0; mf < 4; mf++) {
                uint32_t addr = aBase + ((m0 + mf * 16 + a_row) * KP + k0 + a_col8) * 2;
                ldmx4(a[mf][0], a[mf][1], a[mf][2], a[mf][3], addr);
            }
            uint32_t bfr[4][2];
#pragma unroll
            for (int h = 0; h < 2; h++) {
                uint32_t addr = bBase + ((n0 + h * 16 + b_row) * KP + k0 + b_col8) * 2;
                ldmx4(bfr[h * 2][0], bfr[h * 2][1], bfr[h * 2 + 1][0],
                      bfr[h * 2 + 1][1], addr);
            }
#pragma unroll
            for (int mf = 0; mf < 4; mf++)
#pragma unroll
                for (int nf = 0; nf < 4; nf++)
                    mma16816(acc[mf][nf][0], acc[mf][nf][1], acc[mf][nf][2],
                             acc[mf][nf][3], a[mf][0], a[mf][1], a[mf][2],
                             a[mf][3], bfr[nf][0], bfr[nf][1]);
        }

        // Epilogue for this chunk
        int bcol = c * TN;
        int g = lane >> 2, tg = lane & 3;
#pragma unroll
        for (int mf = 0; mf < 4; mf++) {
            int r0i = m0 + mf * 16 + g;
            int r1i = r0i + 8;
            float w0 = wS[r0i], b0 = biS[r0i];
            float w1 = wS[r1i], b1 = biS[r1i];
            float* o0 = out + (size_t)(brow + r0i) * NL + bcol + n0 + tg * 2;
            float* o1 = out + (size_t)(brow + r1i) * NL + bcol + n0 + tg * 2;
#pragma unroll
            for (int nf = 0; nf < 4; nf++) {
                float2 v0, v1;
                v0.x = acc[mf][nf][0] * w0 + b0;
                v0.y = acc[mf][nf][1] * w0 + b0;
                v1.x = acc[mf][nf][2] * w1 + b1;
                v1.y = acc[mf][nf][3] * w1 + b1;
                *(float2*)(o0 + nf * 8) = v0;
                *(float2*)(o1 + nf * 8) = v1;
            }
        }
        __syncthreads();   // done reading buffer before it is refilled
    }
}

// ---------------------------------------------------------------------------
extern "C" void kernel_launch(void* const* d_in, const int* in_sizes, int n_in,
                              void* d_out, int out_size) {
    const float* x        = (const float*)d_in[0];
    const float* date_vec = (const float*)d_in[1];
    // d_in[2] (conv_w) is dead code in the reference
    const float* convt_w  = (const float*)d_in[3];
    const float* mem_W    = (const float*)d_in[4];
    const float* date_W   = (const float*)d_in[5];
    const float* fcw_w    = (const float*)d_in[6];
    const float* fcw_b    = (const float*)d_in[7];
    const float* fcb_w    = (const float*)d_in[8];
    const float* fcb_b    = (const float*)d_in[9];
    float* out = (float*)d_out;

    cudaFuncSetAttribute(k_fused, cudaFuncAttributeMaxDynamicSharedMemorySize,
                         SMEM_REQ);

    k_prep<<<(NL + 255) / 256, 256>>>(mem_W, convt_w);
    k_fused<<<NB / TM, 256, SMEM_REQ>>>(x, date_vec, date_W, fcw_w, fcw_b,
                                        fcb_w, fcb_b, out);
}

// round 7
// speedup vs baseline: 4.1760x; 1.1493x over previous
#include <cuda_runtime.h>
#include <cuda_bf16.h>
#include <cstdint>

#define NB 32768
#define NL 1024
#define NK 5
#define FEA 1028
#define MD 50
#define DD 32
#define SHRINKF 0.0025f
#define EPSF 1e-12f

#define KE   64            // K padded 50->64, plain bf16
#define KE8  (KE / 8)
#define KP   72            // SMEM pitch in bf16 (144B -> conflict-free ldmatrix)

#define TM 128             // rows per CTA
#define TN 128             // cols per chunk
#define NCHUNK (NL / TN)   // 8

// Scratch (__device__ global; allocation-free rule)
__device__ __align__(16) __nv_bfloat16 g_Be[(size_t)NL * KE];   // 131 KB

__device__ __forceinline__ uint32_t smem_u32(const void* p) {
    uint32_t a;
    asm("{ .reg .u64 t; cvta.to.shared.u64 t, %1; cvt.u32.u64 %0, t; }"
        : "=r"(a) : "l"(p));
    return a;
}
__device__ __forceinline__ void ldmx4(uint32_t& r0, uint32_t& r1,
                                      uint32_t& r2, uint32_t& r3, uint32_t addr) {
    asm volatile("ldmatrix.sync.aligned.m8n8.x4.shared.b16 {%0,%1,%2,%3}, [%4];"
                 : "=r"(r0), "=r"(r1), "=r"(r2), "=r"(r3) : "r"(addr));
}
__device__ __forceinline__ void mma16816(float& c0, float& c1, float& c2, float& c3,
                                         uint32_t a0, uint32_t a1, uint32_t a2,
                                         uint32_t a3, uint32_t b0, uint32_t b1) {
    asm volatile(
        "mma.sync.aligned.m16n8k16.row.col.f32.bf16.bf16.f32 "
        "{%0,%1,%2,%3}, {%4,%5,%6,%7}, {%8,%9}, {%0,%1,%2,%3};"
        : "+f"(c0), "+f"(c1), "+f"(c2), "+f"(c3)
        : "r"(a0), "r"(a1), "r"(a2), "r"(a3), "r"(b0), "r"(b1));
}
__device__ __forceinline__ void cpa16(uint32_t dst, const void* src) {
    asm volatile("cp.async.cg.shared.global [%0], [%1], 16;" :: "r"(dst), "l"(src));
}
__device__ __forceinline__ void cpa_commit() {
    asm volatile("cp.async.commit_group;" ::: "memory");
}
template <int N>
__device__ __forceinline__ void cpa_wait() {
    asm volatile("cp.async.wait_group %0;" :: "n"(N) : "memory");
}

// ---------------------------------------------------------------------------
// Kernel 1: fold transposed conv into mem_W -> bf16, K-major [i][KE].
// One thread per (i, k-pair): 10 loads, one coalesced bf16x2 store.
// ---------------------------------------------------------------------------
__global__ __launch_bounds__(256) void k_prep(const float* __restrict__ mem_W,
                                              const float* __restrict__ convt_w) {
    int idx = blockIdx.x * blockDim.x + threadIdx.x;   // 0 .. NL*KE/2-1
    int k2 = idx & (KE / 2 - 1);
    int i  = idx >> 5;
    float c[NK];
#pragma unroll
    for (int t = 0; t < NK; t++) c[t] = convt_w[NK - 1 - t];
    int k0 = 2 * k2, k1 = k0 + 1;
    float v0 = 0.f, v1 = 0.f;
    if (k0 < MD) {
#pragma unroll
        for (int t = 0; t < NK; t++) v0 += mem_W[k0 * FEA + i + t] * c[t];
    }
    if (k1 < MD) {
#pragma unroll
        for (int t = 0; t < NK; t++) v1 += mem_W[k1 * FEA + i + t] * c[t];
    }
    __nv_bfloat162 p;
    p.x = __float2bfloat16(v0);
    p.y = __float2bfloat16(v1);
    *(__nv_bfloat162*)&g_Be[(size_t)i * KE + k0] = p;
}

// ---------------------------------------------------------------------------
// Fused kernel: per CTA of 128 rows —
//   (a) att -> A tile in SMEM (bf16, KP pitch)
//   (b) weight/bias from x (warp per row-PAIR for 2x MLP), SMEM + out tail
//   (c) 8 column chunks: cp.async B tile (double buffered), warp-MMA,
//       fused affine epilogue store.
// ---------------------------------------------------------------------------
#define SM_A_B   (TM * KP * 2)                        // 18432
#define SM_B_B   (TM * KP * 2)                        // per buffer, 18432
#define OFF_B0   SM_A_B
#define OFF_B1   (SM_A_B + SM_B_B)
#define OFF_FCW  (OFF_B1 + SM_B_B)                    // 55296
#define OFF_FCB  (OFF_FCW + NL * 4)
#define OFF_W    (OFF_FCB + NL * 4)
#define OFF_BI   (OFF_W + TM * 4)
#define SMEM_REQ (OFF_BI + TM * 4)                    // 64512

__global__ __launch_bounds__(256, 2) void k_fused(
    const float* __restrict__ x,
    const float* __restrict__ date_vec,
    const float* __restrict__ date_W,
    const float* __restrict__ fcw_w,
    const float* __restrict__ fcw_b,
    const float* __restrict__ fcb_w,
    const float* __restrict__ fcb_b,
    float* __restrict__ out) {
    extern __shared__ char smc[];
    __nv_bfloat16* As = (__nv_bfloat16*)smc;
    float* fcwS = (float*)(smc + OFF_FCW);
    float* fcbS = (float*)(smc + OFF_FCB);
    float* wS   = (float*)(smc + OFF_W);
    float* biS  = (float*)(smc + OFF_BI);
    float* dW   = (float*)(smc + OFF_B1);   // temp: date_W in B buffer 1

    int tid = threadIdx.x;
    int wid = tid >> 5, lane = tid & 31;
    int brow = blockIdx.x * TM;
    uint32_t smBase = smem_u32(smc);

    // --- Prefetch B chunk 0 into buffer 0 (async, not needed until loop) ---
    for (int i = tid; i < TM * KE8; i += 256) {
        int r = i >> 3, j = i & 7;
        cpa16(smBase + OFF_B0 + (r * KP + j * 8) * 2,
              &g_Be[(size_t)r * KE + j * 8]);
    }
    cpa_commit();

    // --- Load small weights into SMEM ---
    {
        float4* f4 = (float4*)fcwS;
        float4* g4 = (float4*)fcbS;
        f4[tid] = ((const float4*)fcw_w)[tid];
        g4[tid] = ((const float4*)fcb_w)[tid];
        for (int i = tid; i < MD * DD; i += 256) dW[i] = date_W[i];
    }
    __syncthreads();

    // --- Phase A: attention -> A tile (one thread per row, threads 0..127) ---
    if (tid < TM) {
        int b = brow + tid;
        float4 dv[8];
        const float4* dvp = (const float4*)(date_vec + (size_t)b * DD);
#pragma unroll
        for (int i = 0; i < 8; i++) dv[i] = dvp[i];
        float s[MD];
#pragma unroll
        for (int j = 0; j < MD; j++) {
            const float4* w4 = (const float4*)(dW + j * DD);
            float acc = 0.f;
#pragma unroll
            for (int i = 0; i < 8; i++) {
                float4 w = w4[i];
                acc += dv[i].x * w.x + dv[i].y * w.y + dv[i].z * w.z + dv[i].w * w.w;
            }
            s[j] = acc;
        }
        float m = -1e30f;
#pragma unroll
        for (int j = 0; j < MD; j++) m = fmaxf(m, s[j]);
        float sum = 0.f;
#pragma unroll
        for (int j = 0; j < MD; j++) { s[j] = expf(s[j] - m); sum += s[j]; }
        float inv = 1.f / sum;
        float sa = 0.f;
#pragma unroll
        for (int j = 0; j < MD; j++) {
            float a = s[j] * inv;
            float t = a - SHRINKF;
            float v = fmaxf(t, 0.f) * a / (fabsf(t) + EPSF);
            s[j] = v;
            sa += v;   // v >= 0
        }
        float inv2 = 1.f / (sa + EPSF);
        __nv_bfloat16* row = As + tid * KP;
#pragma unroll
        for (int j = 0; j < KE; j++)
            row[j] = __float2bfloat16(j < MD ? s[j] * inv2 : 0.f);
    }

    // --- Phase W: weight/bias (warp per ROW-PAIR: 16 LDG.128 in flight) ---
    {
        const float4* fw4 = (const float4*)fcwS;
        const float4* fb4 = (const float4*)fcbS;
        float w0c = fcw_b[0], b0c = fcb_b[0];
#pragma unroll 1
        for (int rp = 0; rp < 8; rp++) {
            int row0 = wid * 16 + rp * 2;
            int row1 = row0 + 1;
            const float4* xr0 = (const float4*)(x + (size_t)(brow + row0) * NL);
            const float4* xr1 = (const float4*)(x + (size_t)(brow + row1) * NL);
            float wa0 = 0.f, ba0 = 0.f, wa1 = 0.f, ba1 = 0.f;
#pragma unroll
            for (int i = 0; i < 8; i++) {
                float4 xv0 = xr0[i * 32 + lane];
                float4 xv1 = xr1[i * 32 + lane];
                float4 fw = fw4[i * 32 + lane];
                float4 fb = fb4[i * 32 + lane];
                wa0 += xv0.x * fw.x + xv0.y * fw.y + xv0.z * fw.z + xv0.w * fw.w;
                ba0 += xv0.x * fb.x + xv0.y * fb.y + xv0.z * fb.z + xv0.w * fb.w;
                wa1 += xv1.x * fw.x + xv1.y * fw.y + xv1.z * fw.z + xv1.w * fw.w;
                ba1 += xv1.x * fb.x + xv1.y * fb.y + xv1.z * fb.z + xv1.w * fb.w;
            }
#pragma unroll
            for (int o = 16; o; o >>= 1) {
                wa0 += __shfl_xor_sync(~0u, wa0, o);
                ba0 += __shfl_xor_sync(~0u, ba0, o);
                wa1 += __shfl_xor_sync(~0u, wa1, o);
                ba1 += __shfl_xor_sync(~0u, ba1, o);
            }
            if (lane == 0) {
                float wv0 = tanhf(wa0 + w0c) * 0.5f + 1.0f;
                float bv0 = tanhf(ba0 + b0c) * 0.5f;
                float wv1 = tanhf(wa1 + w0c) * 0.5f + 1.0f;
                float bv1 = tanhf(ba1 + b0c) * 0.5f;
                wS[row0] = wv0;  biS[row0] = bv0;
                wS[row1] = wv1;  biS[row1] = bv1;
                out[(size_t)NB * NL + brow + row0] = wv0;
                out[(size_t)NB * NL + NB + brow + row0] = bv0;
                out[(size_t)NB * NL + brow + row1] = wv1;
                out[(size_t)NB * NL + NB + brow + row1] = bv1;
            }
        }
    }
    __syncthreads();   // A tile, wS/biS ready; dW dead (buf1 reusable)

    // --- Phase G: chunk loop with double-buffered B ---
    int warp_m = wid >> 2, warp_n = wid & 3;
    int m0 = warp_m * 64, n0 = warp_n * 32;
    uint32_t aBase = smBase;

    int a_row = lane & 15;
    int a_col8 = (lane >> 4) * 8;
    int b_row = (lane & 7) + ((lane >> 4) << 3);
    int b_col8 = ((lane >> 3) & 1) * 8;

#pragma unroll 1
    for (int c = 0; c < NCHUNK; c++) {
        // Prefetch next chunk into the other buffer
        if (c + 1 < NCHUNK) {
            uint32_t dstb = smBase + ((c + 1) & 1 ? OFF_B1 : OFF_B0);
            for (int i = tid; i < TM * KE8; i += 256) {
                int r = i >> 3, j = i & 7;
                cpa16(dstb + (r * KP + j * 8) * 2,
                      &g_Be[(size_t)((c + 1) * TN + r) * KE + j * 8]);
            }
            cpa_commit();
            cpa_wait<1>();
        } else {
            cpa_wait<0>();
        }
        __syncthreads();   // current buffer ready for all warps

        uint32_t bBase = smBase + (c & 1 ? OFF_B1 : OFF_B0);

        float acc[4][4][4];
#pragma unroll
        for (int mf = 0; mf < 4; mf++)
#pragma unroll
            for (int nf = 0; nf < 4; nf++)
#pragma unroll
                for (int q = 0; q < 4; q++) acc[mf][nf][q] = 0.f;

#pragma unroll
        for (int ks = 0; ks < KE / 16; ks++) {
            int k0 = ks * 16;
            uint32_t a[4][4];
#pragma unroll
            for (int mf = 0; mf < 4; mf++) {
                uint32_t addr = aBase + ((m0 + mf * 16 + a_row) * KP + k0 + a_col8) * 2;
                ldmx4(a[mf][0], a[mf][1], a[mf][2], a[mf][3], addr);
            }
            uint32_t bfr[4][2];
#pragma unroll
            for (int h = 0; h < 2; h++) {
                uint32_t addr = bBase + ((n0 + h * 16 + b_row) * KP + k0 + b_col8) * 2;
                ldmx4(bfr[h * 2][0], bfr[h * 2][1], bfr[h * 2 + 1][0],
                      bfr[h * 2 + 1][1], addr);
            }
#pragma unroll
            for (int mf = 0; mf < 4; mf++)
#pragma unroll
                for (int nf = 0; nf < 4; nf++)
                    mma16816(acc[mf][nf][0], acc[mf][nf][1], acc[mf][nf][2],
                             acc[mf][nf][3], a[mf][0], a[mf][1], a[mf][2],
                             a[mf][3], bfr[nf][0], bfr[nf][1]);
        }

        // Epilogue for this chunk
        int bcol = c * TN;
        int g = lane >> 2, tg = lane & 3;
#pragma unroll
        for (int mf = 0; mf < 4; mf++) {
            int r0i = m0 + mf * 16 + g;
            int r1i = r0i + 8;
            float w0 = wS[r0i], b0 = biS[r0i];
            float w1 = wS[r1i], b1 = biS[r1i];
            float* o0 = out + (size_t)(brow + r0i) * NL + bcol + n0 + tg * 2;
            float* o1 = out + (size_t)(brow + r1i) * NL + bcol + n0 + tg * 2;
#pragma unroll
            for (int nf = 0; nf < 4; nf++) {
                float2 v0, v1;
                v0.x = acc[mf][nf][0] * w0 + b0;
                v0.y = acc[mf][nf][1] * w0 + b0;
                v1.x = acc[mf][nf][2] * w1 + b1;
                v1.y = acc[mf][nf][3] * w1 + b1;
                *(float2*)(o0 + nf * 8) = v0;
                *(float2*)(o1 + nf * 8) = v1;
            }
        }
        __syncthreads();   // done reading buffer before it is refilled
    }
}

// ---------------------------------------------------------------------------
extern "C" void kernel_launch(void* const* d_in, const int* in_sizes, int n_in,
                              void* d_out, int out_size) {
    const float* x        = (const float*)d_in[0];
    const float* date_vec = (const float*)d_in[1];
    // d_in[2] (conv_w) is dead code in the reference
    const float* convt_w  = (const float*)d_in[3];
    const float* mem_W    = (const float*)d_in[4];
    const float* date_W   = (const float*)d_in[5];
    const float* fcw_w    = (const float*)d_in[6];
    const float* fcw_b    = (const float*)d_in[7];
    const float* fcb_w    = (const float*)d_in[8];
    const float* fcb_b    = (const float*)d_in[9];
    float* out = (float*)d_out;

    cudaFuncSetAttribute(k_fused, cudaFuncAttributeMaxDynamicSharedMemorySize,
                         SMEM_REQ);

    k_prep<<<NL * KE / 2 / 256, 256>>>(mem_W, convt_w);
    k_fused<<<NB / TM, 256, SMEM_REQ>>>(x, date_vec, date_W, fcw_w, fcw_b,
                                        fcb_w, fcb_b, out);
}